// round 6
// baseline (speedup 1.0000x reference)
#include <cuda_runtime.h>
#include <math.h>

// Problem constants
#define BB 4
#define CC 128
#define HH 240
#define WW 320
#define NN 1024
#define NPTS (BB * NN)

__device__ float g_e1[NPTS];
__device__ float g_ld[NPTS];
__device__ unsigned int g_count = 0;

__device__ __forceinline__ float warp_sum(float v) {
#pragma unroll
    for (int o = 16; o; o >>= 1) v += __shfl_xor_sync(0xffffffffu, v, o);
    return v;
}

// i is warp-uniform (0..3)
__device__ __forceinline__ float pick4(float4 v, int i) {
    float r = v.x;
    if (i == 1) r = v.y;
    else if (i == 2) r = v.z;
    else if (i == 3) r = v.w;
    return r;
}
// i is warp-uniform (0..7)
__device__ __forceinline__ float pick8(float4 a, float4 b, int i) {
    return (i < 4) ? pick4(a, i) : pick4(b, i - 4);
}

__global__ __launch_bounds__(128) void gnloss_point_kernel(
    const float* __restrict__ Fa, const float* __restrict__ Fb,
    const float* __restrict__ ma, const float* __restrict__ mb,
    const float* __restrict__ noise, float* __restrict__ out)
{
    const int p = blockIdx.x;          // point index, 0..4095
    const int b = p >> 10;             // p / NN
    const int c = threadIdx.x;         // channel

    const float invL = 1.0f / 8.0f;    // 1/LEVEL
    const float2 mav = ((const float2*)ma)[p];
    const float2 mbv = ((const float2*)mb)[p];
    const float2 nzv = ((const float2*)noise)[p];
    const float xa  = mav.x * invL;
    const float ya  = mav.y * invL;
    const float ubx = mbv.x * invL;
    const float uby = mbv.y * invL;
    const float nx  = nzv.x;
    const float ny  = nzv.y;
    const float xs  = 2.0f * nx - 1.0f + ubx;
    const float ys  = 2.0f * ny - 1.0f + uby;

    // ---- f_t: bilinear sample of F_a at (xa, ya) ----
    const float* pa = Fa + (size_t)(b * CC + c) * (HH * WW);
    float fx0 = floorf(xa), fy0 = floorf(ya);
    float wxa = xa - fx0,  wya = ya - fy0;
    int ax0 = min(max((int)fx0, 0), WW - 1);
    int ax1 = min(ax0 + 1, WW - 1);
    int ay0 = min(max((int)fy0, 0), HH - 1);
    int ay1 = min(ay0 + 1, HH - 1);
    // Vectorized: one aligned float4 covers ax0 (and usually ax1).
    int baseA = min(ax0 & ~3, WW - 4);   // 16B-aligned, in-row
    int ja0 = ax0 - baseA;               // 0..3, uniform
    int ja1 = ax1 - baseA;               // 0..4, uniform
    const float* ra0 = pa + ay0 * WW;
    const float* ra1 = pa + ay1 * WW;
    float4 qa0 = *(const float4*)(ra0 + baseA);
    float4 qa1 = *(const float4*)(ra1 + baseA);
    float a00 = pick4(qa0, ja0);
    float a10 = pick4(qa1, ja0);
    float a01 = (ja1 <= 3) ? pick4(qa0, ja1) : ra0[ax1];
    float a11 = (ja1 <= 3) ? pick4(qa1, ja1) : ra1[ax1];
    float ft = a00 * (1.0f - wxa) * (1.0f - wya) + a01 * wxa * (1.0f - wya)
             + a10 * (1.0f - wxa) * wya          + a11 * wxa * wya;

    // ---- F_b neighborhood for f_s, Jx, Jy ----
    const float* pb = Fb + (size_t)(b * CC + c) * (HH * WW);
    float gx0f = floorf(xs), gy0f = floorf(ys);
    float wx = xs - gx0f, wy = ys - gy0f;
    int x0 = min(max((int)gx0f, 0), WW - 1);
    int x1 = min(x0 + 1, WW - 1);
    int y0 = min(max((int)gy0f, 0), HH - 1);
    int y1 = min(y0 + 1, HH - 1);
    int xm = max(x0 - 1, 0), xp = min(x1 + 1, WW - 1);
    int ym = max(y0 - 1, 0), yp = min(y1 + 1, HH - 1);

    const float* r0 = pb + y0 * WW;
    const float* r1 = pb + y1 * WW;
    const float* rm = pb + ym * WW;
    const float* rp = pb + yp * WW;

    // Rows y0/y1: need xm, x0, x1, xp — all inside two aligned float4s at
    // base4 = min(xm & ~3, W-8). (Clamped base keeps the 32B read in-row;
    // xp - base4 <= 7 holds in every clamp case.)
    int base4 = min(xm & ~3, WW - 8);
    int im = xm - base4, i0 = x0 - base4, i1 = x1 - base4, ip = xp - base4;
    const float4* q0 = (const float4*)(r0 + base4);
    const float4* q1 = (const float4*)(r1 + base4);
    float4 q0a = q0[0], q0b = q0[1];
    float4 q1a = q1[0], q1b = q1[1];
    float vm0 = pick8(q0a, q0b, im), v00 = pick8(q0a, q0b, i0);
    float v01 = pick8(q0a, q0b, i1), vp0 = pick8(q0a, q0b, ip);
    float vm1 = pick8(q1a, q1b, im), v10 = pick8(q1a, q1b, i0);
    float v11 = pick8(q1a, q1b, i1), vp1 = pick8(q1a, q1b, ip);

    // Rows ym/yp: need x0, x1 — one aligned float4 (+ rare uniform scalar top-up).
    int base2 = min(x0 & ~3, WW - 4);
    int j0 = x0 - base2, j1 = x1 - base2;   // j0 in 0..3, j1 in 0..4
    float4 qm = *(const float4*)(rm + base2);
    float4 qp = *(const float4*)(rp + base2);
    float um0 = pick4(qm, j0);
    float up0 = pick4(qp, j0);
    float um1 = (j1 <= 3) ? pick4(qm, j1) : rm[x1];
    float up1 = (j1 <= 3) ? pick4(qp, j1) : rp[x1];

    // Deduped xq/yq values (xq = max(x1-1,0), yq = max(y1-1,0)):
    float vq0 = (x1 > x0) ? v00 : vm0;
    float vq1 = (x1 > x0) ? v10 : vm1;
    float uq0 = (y1 > y0) ? v00 : um0;
    float uq1 = (y1 > y0) ? v01 : um1;

    float w00 = (1.0f - wx) * (1.0f - wy);
    float w01 = wx * (1.0f - wy);
    float w10 = (1.0f - wx) * wy;
    float w11 = wx * wy;

    float fs = v00 * w00 + v01 * w01 + v10 * w10 + v11 * w11;

    // gx(y, x) = 0.5*(f(y, min(x+1,W-1)) - f(y, max(x-1,0))); min(x0+1,W-1)==x1.
    float gx00 = 0.5f * (v01 - vm0);
    float gx01 = 0.5f * (vp0 - vq0);
    float gx10 = 0.5f * (v11 - vm1);
    float gx11 = 0.5f * (vp1 - vq1);
    float Jx = gx00 * w00 + gx01 * w01 + gx10 * w10 + gx11 * w11;

    // gy(y, x) = 0.5*(f(min(y+1,H-1),x) - f(max(y-1,0),x)); min(y0+1,H-1)==y1.
    float gy00 = 0.5f * (v10 - um0);
    float gy01 = 0.5f * (v11 - um1);
    float gy10 = 0.5f * (up0 - uq0);
    float gy11 = 0.5f * (up1 - uq1);
    float Jy = gy00 * w00 + gy01 * w01 + gy10 * w10 + gy11 * w11;

    // ---- reductions ----
    __shared__ float sh[4][8];
    __shared__ unsigned s_last;
    const int warp = c >> 5, lane = c & 31;

    float st = warp_sum(ft * ft);
    float ss = warp_sum(fs * fs);
    if (lane == 0) { sh[warp][0] = st; sh[warp][1] = ss; }
    __syncthreads();
    float nt = sqrtf(sh[0][0] + sh[1][0] + sh[2][0] + sh[3][0]);
    float ns = sqrtf(sh[0][1] + sh[1][1] + sh[2][1] + sh[3][1]);
    nt = fmaxf(nt, 1e-12f);
    ns = fmaxf(ns, 1e-12f);
    float r = fs / ns - ft / nt;
    __syncthreads();   // protect sh before reuse

    float sA = warp_sum(Jx * Jx);
    float sB = warp_sum(Jx * Jy);
    float sD = warp_sum(Jy * Jy);
    float s0 = warp_sum(Jx * r);
    float s1 = warp_sum(Jy * r);
    if (lane == 0) {
        sh[warp][2] = sA; sh[warp][3] = sB; sh[warp][4] = sD;
        sh[warp][5] = s0; sh[warp][6] = s1;
    }
    __syncthreads();

    if (c == 0) {
        const float EPSF = 1e-9f;
        float A  = sh[0][2] + sh[1][2] + sh[2][2] + sh[3][2] + EPSF;
        float Bo = sh[0][3] + sh[1][3] + sh[2][3] + sh[3][3];
        float D  = sh[0][4] + sh[1][4] + sh[2][4] + sh[3][4] + EPSF;
        float b0 = sh[0][5] + sh[1][5] + sh[2][5] + sh[3][5];
        float b1 = sh[0][6] + sh[1][6] + sh[2][6] + sh[3][6];
        float det = A * D - Bo * Bo;
        float inv = 1.0f / det;
        float h0 = (D * b0 - Bo * b1) * inv;     // (Hinv @ b)[0]
        float h1 = (A * b1 - Bo * b0) * inv;     // (Hinv @ b)[1]
        // diff = ub - miu = ub - xs + Hinv@b = (1 - 2*noise) + Hinv@b
        float d0 = (1.0f - 2.0f * nx) + h0;
        float d1 = (1.0f - 2.0f * ny) + h1;
        float e1 = 0.5f * (A * d0 * d0 + 2.0f * Bo * d0 * d1 + D * d1 * d1);
        g_e1[p] = e1;
        g_ld[p] = logf(det);
        __threadfence();
        unsigned prev = atomicAdd(&g_count, 1u);
        s_last = (prev == (unsigned)(NPTS - 1)) ? 1u : 0u;
    }
    __syncthreads();

    // ---- last block performs the deterministic global reduction ----
    if (s_last) {
        __threadfence();   // acquire all other blocks' g_e1/g_ld writes
        __shared__ double r1h[128], r2h[128];
        double t1 = 0.0, t2 = 0.0;
#pragma unroll 8
        for (int i = c; i < NPTS; i += 128) {
            t1 += (double)g_e1[i];
            t2 += (double)g_ld[i];
        }
        r1h[c] = t1; r2h[c] = t2;
        __syncthreads();
        for (int o = 64; o; o >>= 1) {
            if (c < o) { r1h[c] += r1h[c + o]; r2h[c] += r2h[c + o]; }
            __syncthreads();
        }
        if (c == 0) {
            double e1 = r1h[0];
            double e2 = (double)NPTS * log(2.0 * M_PI) - 0.5 * r2h[0];
            double e  = e1 + (2.0 / 7.0) * e2;
            out[0] = (float)(0.3 * e);
            out[1] = (float)e1;
            out[2] = (float)e2;
            g_count = 0;   // reset for next graph replay
        }
    }
}

extern "C" void kernel_launch(void* const* d_in, const int* in_sizes, int n_in,
                              void* d_out, int out_size)
{
    const float* Fa    = (const float*)d_in[0];
    const float* Fb    = (const float*)d_in[1];
    const float* ma    = (const float*)d_in[2];
    const float* mb    = (const float*)d_in[3];
    const float* noise = (const float*)d_in[4];
    float* out = (float*)d_out;

    gnloss_point_kernel<<<NPTS, 128>>>(Fa, Fb, ma, mb, noise, out);
}

// round 7
// speedup vs baseline: 1.0537x; 1.0537x over previous
#include <cuda_runtime.h>
#include <math.h>

// Problem constants
#define BB 4
#define CC 128
#define HH 240
#define WW 320
#define NN 1024
#define NPTS (BB * NN)
#define NSLICE 4
#define SLICE_C 32          // channels per slice

// Per-(point,slice) partials: 9 floats packed in 3 float4
__device__ float4 g_part[NPTS * NSLICE * 3];
// Per-block partials for the final sum (32 stage-2 blocks)
__device__ double g_bp_e1[32];
__device__ double g_bp_ld[32];
__device__ unsigned int g_count = 0;

__device__ __forceinline__ float warp_sum(float v) {
#pragma unroll
    for (int o = 16; o; o >>= 1) v += __shfl_xor_sync(0xffffffffu, v, o);
    return v;
}

// ---------------- Stage 1: gather + per-(point,slice) partial sums ----------------
// Grid: NSLICE * (NPTS/4) blocks of 128 threads, slice-major.
// Block handles 4 points x one 32-channel slice; each warp owns one point.
__global__ __launch_bounds__(128) void gnloss_stage1(
    const float* __restrict__ Fa, const float* __restrict__ Fb,
    const float* __restrict__ ma, const float* __restrict__ mb,
    const float* __restrict__ noise)
{
    const int bid   = blockIdx.x;
    const int slice = bid >> 10;           // 0..3  (slice-major ordering)
    const int pg    = bid & 1023;          // point group
    const int w     = threadIdx.x >> 5;
    const int lane  = threadIdx.x & 31;
    const int p     = pg * 4 + w;          // point 0..4095
    const int b     = p >> 10;
    const int c     = slice * SLICE_C + lane;

    const float invL = 1.0f / 8.0f;
    const float2 mav = ((const float2*)ma)[p];
    const float2 mbv = ((const float2*)mb)[p];
    const float2 nzv = ((const float2*)noise)[p];
    const float xa = mav.x * invL, ya = mav.y * invL;
    const float xs = 2.0f * nzv.x - 1.0f + mbv.x * invL;
    const float ys = 2.0f * nzv.y - 1.0f + mbv.y * invL;

    // ---- f_t: bilinear sample of F_a ----
    const float* pa = Fa + (size_t)(b * CC + c) * (HH * WW);
    float fx0 = floorf(xa), fy0 = floorf(ya);
    float wxa = xa - fx0,  wya = ya - fy0;
    int ax0 = min(max((int)fx0, 0), WW - 1);
    int ax1 = min(ax0 + 1, WW - 1);
    int ay0 = min(max((int)fy0, 0), HH - 1);
    int ay1 = min(ay0 + 1, HH - 1);
    float a00 = pa[ay0 * WW + ax0], a01 = pa[ay0 * WW + ax1];
    float a10 = pa[ay1 * WW + ax0], a11 = pa[ay1 * WW + ax1];
    float ft = a00 * (1.0f - wxa) * (1.0f - wya) + a01 * wxa * (1.0f - wya)
             + a10 * (1.0f - wxa) * wya          + a11 * wxa * wya;

    // ---- F_b neighborhood: 12 deduped scalar loads ----
    const float* pb = Fb + (size_t)(b * CC + c) * (HH * WW);
    float gx0f = floorf(xs), gy0f = floorf(ys);
    float wx = xs - gx0f, wy = ys - gy0f;
    int x0 = min(max((int)gx0f, 0), WW - 1);
    int x1 = min(x0 + 1, WW - 1);
    int y0 = min(max((int)gy0f, 0), HH - 1);
    int y1 = min(y0 + 1, HH - 1);
    int xm = max(x0 - 1, 0), xp = min(x1 + 1, WW - 1);
    int ym = max(y0 - 1, 0), yp = min(y1 + 1, HH - 1);

    const float* r0 = pb + y0 * WW;
    const float* r1 = pb + y1 * WW;
    const float* rm = pb + ym * WW;
    const float* rp = pb + yp * WW;
    float vm0 = r0[xm], v00 = r0[x0], v01 = r0[x1], vp0 = r0[xp];
    float vm1 = r1[xm], v10 = r1[x0], v11 = r1[x1], vp1 = r1[xp];
    float um0 = rm[x0], um1 = rm[x1];
    float up0 = rp[x0], up1 = rp[x1];

    // Dedup: xq = max(x1-1,0) == x0 unless x1==x0 (then == xm). Same for rows.
    float vq0 = (x1 > x0) ? v00 : vm0;
    float vq1 = (x1 > x0) ? v10 : vm1;
    float uq0 = (y1 > y0) ? v00 : um0;
    float uq1 = (y1 > y0) ? v01 : um1;

    float w00 = (1.0f - wx) * (1.0f - wy);
    float w01 = wx * (1.0f - wy);
    float w10 = (1.0f - wx) * wy;
    float w11 = wx * wy;

    float fs = v00 * w00 + v01 * w01 + v10 * w10 + v11 * w11;

    float Jx = (0.5f * (v01 - vm0)) * w00 + (0.5f * (vp0 - vq0)) * w01
             + (0.5f * (v11 - vm1)) * w10 + (0.5f * (vp1 - vq1)) * w11;
    float Jy = (0.5f * (v10 - um0)) * w00 + (0.5f * (v11 - um1)) * w01
             + (0.5f * (up0 - uq0)) * w10 + (0.5f * (up1 - uq1)) * w11;

    // ---- 9 warp reductions over this 32-channel slice ----
    float sft2 = warp_sum(ft * ft);
    float sfs2 = warp_sum(fs * fs);
    float sjxx = warp_sum(Jx * Jx);
    float sjxy = warp_sum(Jx * Jy);
    float sjyy = warp_sum(Jy * Jy);
    float sjxfs = warp_sum(Jx * fs);
    float sjxft = warp_sum(Jx * ft);
    float sjyfs = warp_sum(Jy * fs);
    float sjyft = warp_sum(Jy * ft);

    if (lane == 0) {
        float4* dst = &g_part[(p * NSLICE + slice) * 3];
        dst[0] = make_float4(sft2, sfs2, sjxx, sjxy);
        dst[1] = make_float4(sjyy, sjxfs, sjxft, sjyfs);
        dst[2] = make_float4(sjyft, 0.0f, 0.0f, 0.0f);
    }
}

// ---------------- Stage 2: combine slices, per-point solve, global sum ----------------
// Grid: 32 blocks x 128 threads; thread t handles point p = bid*128 + tid.
__global__ __launch_bounds__(128) void gnloss_stage2(
    const float* __restrict__ noise, float* __restrict__ out)
{
    const int tid = threadIdx.x;
    const int p = blockIdx.x * 128 + tid;

    float sft2 = 0, sfs2 = 0, sjxx = 0, sjxy = 0, sjyy = 0;
    float sjxfs = 0, sjxft = 0, sjyfs = 0, sjyft = 0;
#pragma unroll
    for (int s = 0; s < NSLICE; s++) {
        const float4* src = &g_part[(p * NSLICE + s) * 3];
        float4 q0 = src[0], q1 = src[1], q2 = src[2];
        sft2 += q0.x;  sfs2 += q0.y;  sjxx += q0.z;  sjxy += q0.w;
        sjyy += q1.x;  sjxfs += q1.y; sjxft += q1.z; sjyfs += q1.w;
        sjyft += q2.x;
    }

    const float2 nzv = ((const float2*)noise)[p];
    float nt = fmaxf(sqrtf(sft2), 1e-12f);
    float ns = fmaxf(sqrtf(sfs2), 1e-12f);

    const float EPSF = 1e-9f;
    float A  = sjxx + EPSF;
    float Bo = sjxy;
    float D  = sjyy + EPSF;
    float b0 = sjxfs / ns - sjxft / nt;
    float b1 = sjyfs / ns - sjyft / nt;
    float det = A * D - Bo * Bo;
    float inv = 1.0f / det;
    float h0 = (D * b0 - Bo * b1) * inv;
    float h1 = (A * b1 - Bo * b0) * inv;
    // diff = ub - miu = (1 - 2*noise) + Hinv@b
    float d0 = (1.0f - 2.0f * nzv.x) + h0;
    float d1 = (1.0f - 2.0f * nzv.y) + h1;
    float e1 = 0.5f * (A * d0 * d0 + 2.0f * Bo * d0 * d1 + D * d1 * d1);
    float ld = logf(det);

    // ---- block reduction (doubles) ----
    __shared__ double r1h[128], r2h[128];
    __shared__ unsigned s_last;
    r1h[tid] = (double)e1;
    r2h[tid] = (double)ld;
    __syncthreads();
    for (int o = 64; o; o >>= 1) {
        if (tid < o) { r1h[tid] += r1h[tid + o]; r2h[tid] += r2h[tid + o]; }
        __syncthreads();
    }
    if (tid == 0) {
        g_bp_e1[blockIdx.x] = r1h[0];
        g_bp_ld[blockIdx.x] = r2h[0];
        __threadfence();
        unsigned prev = atomicAdd(&g_count, 1u);
        s_last = (prev == 31u) ? 1u : 0u;
    }
    __syncthreads();

    if (s_last) {
        __threadfence();
        if (tid == 0) {
            double e1s = 0.0, lds = 0.0;
#pragma unroll
            for (int i = 0; i < 32; i++) { e1s += g_bp_e1[i]; lds += g_bp_ld[i]; }
            double e2 = (double)NPTS * log(2.0 * M_PI) - 0.5 * lds;
            double e  = e1s + (2.0 / 7.0) * e2;
            out[0] = (float)(0.3 * e);
            out[1] = (float)e1s;
            out[2] = (float)e2;
            g_count = 0;   // reset for next graph replay
        }
    }
}

extern "C" void kernel_launch(void* const* d_in, const int* in_sizes, int n_in,
                              void* d_out, int out_size)
{
    const float* Fa    = (const float*)d_in[0];
    const float* Fb    = (const float*)d_in[1];
    const float* ma    = (const float*)d_in[2];
    const float* mb    = (const float*)d_in[3];
    const float* noise = (const float*)d_in[4];
    float* out = (float*)d_out;

    gnloss_stage1<<<NSLICE * (NPTS / 4), 128>>>(Fa, Fb, ma, mb, noise);
    gnloss_stage2<<<32, 128>>>(noise, out);
}